// round 8
// baseline (speedup 1.0000x reference)
#include <cuda_runtime.h>

// TT-linear: y = x @ W^T + bias
//   c0: [1,32(o0),32(i0),4(r1)]  c1: [4(r1),16(o1),16(i1),4(r2)]  c2: [4(r2),16(o2),16(i2),1]
//
// Kernel 0: out = bias (broadcast).
// Kernel 1: grid 256 = (token, i0-half), 512 thr = (z, o1, o2), 2 CTAs/SM (32 warps/SM).
//   z in {0,1} splits r2-pairs in steps 1-2 and the o0-range in step 3.
//   per slice: step2 (B-partial over own r2-pair) -> swap partials via sB -> step3 (own
//   o0-half) -> step1 for next slice (own r2-pair) ; 2 syncs/slice.
//   Epilogue: RED.ADD y into out (bias already there).

#define THREADS 512

typedef unsigned long long u64;

__device__ __forceinline__ u64 pk2(float lo, float hi) {
    u64 r;
    asm("mov.b64 %0, {%1, %2};" : "=l"(r) : "f"(lo), "f"(hi));
    return r;
}
__device__ __forceinline__ void unpk(u64 v, float& lo, float& hi) {
    asm("mov.b64 {%0, %1}, %2;" : "=f"(lo), "=f"(hi) : "l"(v));
}
__device__ __forceinline__ u64 fma2(u64 a, u64 b, u64 c) {
    u64 d;
    asm("fma.rn.f32x2 %0, %1, %2, %3;" : "=l"(d) : "l"(a), "l"(b), "l"(c));
    return d;
}
__device__ __forceinline__ u64 add2(u64 a, u64 b) {
    u64 d;
    asm("add.rn.f32x2 %0, %1, %2;" : "=l"(d) : "l"(a), "l"(b));
    return d;
}
__device__ __forceinline__ float hadd(u64 v) {
    float lo, hi;
    unpk(v, lo, hi);
    return lo + hi;
}

__global__ __launch_bounds__(THREADS, 2)
void tt_partial_kernel(const float* __restrict__ x,
                       const float* __restrict__ g0,
                       const float* __restrict__ g1,
                       const float* __restrict__ g2,
                       float* __restrict__ out)
{
    __shared__ __align__(16) float sc0[2048];    // [it][r1][z][o0']   (this half's 16 i0)
    __shared__ __align__(16) float sc1[4096];    // [z][o1][i1][r1][j] (j = r2 within pair)
    __shared__ __align__(16) float sc2[1024];    // [i2][o2][z][j]
    __shared__ __align__(16) float sA[2][1024];  // [i1][o2][z-pair as u64]
    __shared__ __align__(16) float sX[2][256];   // raw x slice
    __shared__ __align__(16) float sB[2048];     // [z][o1][o2][r1] partials

    const int tid    = threadIdx.x;
    const int token  = blockIdx.x & 127;
    const int half   = blockIdx.x >> 7;
    const int z      = tid >> 8;
    const int rest   = tid & 255;
    const int o1     = rest >> 4;
    const int o2     = rest & 15;
    const int i0base = half * 16;

    // ---- core relayout into smem (THREADS = 512 stride) ----
    for (int idx = tid; idx < 2048; idx += THREADS) {
        int o0p = idx & 15, z0 = (idx >> 4) & 1, r1 = (idx >> 5) & 3, it = idx >> 7;
        sc0[idx] = g0[((16 * z0 + o0p) * 32 + i0base + it) * 4 + r1];
    }
    for (int idx = tid; idx < 4096; idx += THREADS) {
        int j = idx & 1, r1 = (idx >> 1) & 3, i1 = (idx >> 3) & 15,
            o1g = (idx >> 7) & 15, z1 = (idx >> 11) & 1;
        sc1[idx] = g1[((r1 * 16 + o1g) * 16 + i1) * 4 + 2 * z1 + j];
    }
    for (int idx = tid; idx < 1024; idx += THREADS) {
        int j = idx & 1, z2 = (idx >> 1) & 1, o2g = (idx >> 2) & 15, i2 = idx >> 6;
        sc2[idx] = g2[((2 * z2 + j) * 16 + o2g) * 16 + i2];
    }

    const float* xrow = x + token * 8192;
    if (tid < 256) sX[0][tid] = xrow[i0base * 256 + tid];

    u64 yp[8];                           // y[16z .. 16z+16) as packed o0' pairs
    #pragma unroll
    for (int i = 0; i < 8; i++) yp[i] = 0ull;

    const int aoff  = (o1 * 16 + o2) * 4 + z * 2;   // producer slot in sA (i1 = o1 role)
    const int c1off = z * 2048 + o1 * 128;           // this thread's c1 base

    __syncthreads();

    // ---- prologue: step1 for slice 0 into sA[0] ----
    {
        const float4* xq = reinterpret_cast<const float4*>(&sX[0][o1 * 16]);
        float4 x0 = xq[0], x1 = xq[1], x2 = xq[2], x3 = xq[3];
        float xs[16] = { x0.x,x0.y,x0.z,x0.w, x1.x,x1.y,x1.z,x1.w,
                         x2.x,x2.y,x2.z,x2.w, x3.x,x3.y,x3.z,x3.w };
        u64 acc0 = 0ull, acc1 = 0ull;
        #pragma unroll
        for (int i2 = 0; i2 < 16; i2 += 2) {
            u64 c0v = *reinterpret_cast<const u64*>(&sc2[i2 * 64 + o2 * 4 + z * 2]);
            u64 c1v = *reinterpret_cast<const u64*>(&sc2[(i2 + 1) * 64 + o2 * 4 + z * 2]);
            acc0 = fma2(pk2(xs[i2], xs[i2]), c0v, acc0);
            acc1 = fma2(pk2(xs[i2 + 1], xs[i2 + 1]), c1v, acc1);
        }
        *reinterpret_cast<u64*>(&sA[0][aoff]) = add2(acc0, acc1);
    }
    float xnext = 0.f;
    if (tid < 256) xnext = xrow[(i0base + 1) * 256 + tid];
    __syncthreads();

    for (int k = 0; k < 16; k++) {
        // ---- step 2: B-partial[r1] over own r2-pair, all i1 (4 chains depth 16) ----
        const float* A = sA[k & 1];
        u64 acc[4] = { 0ull, 0ull, 0ull, 0ull };
        #pragma unroll
        for (int i1 = 0; i1 < 16; i1++) {
            u64 av = *reinterpret_cast<const u64*>(&A[(i1 * 16 + o2) * 4 + z * 2]);
            const ulonglong2* cp = reinterpret_cast<const ulonglong2*>(&sc1[c1off + i1 * 8]);
            ulonglong2 cA = cp[0];               // r1 = 0, 1
            ulonglong2 cB = cp[1];               // r1 = 2, 3
            acc[0] = fma2(av, cA.x, acc[0]);
            acc[1] = fma2(av, cA.y, acc[1]);
            acc[2] = fma2(av, cB.x, acc[2]);
            acc[3] = fma2(av, cB.y, acc[3]);
        }
        float p0 = hadd(acc[0]), p1 = hadd(acc[1]), p2 = hadd(acc[2]), p3 = hadd(acc[3]);
        {
            float4 st; st.x = p0; st.y = p1; st.z = p2; st.w = p3;
            *reinterpret_cast<float4*>(&sB[(z * 256 + rest) * 4]) = st;
        }
        if (k < 15 && tid < 256) sX[(k + 1) & 1][tid] = xnext;
        __syncthreads();                         // S1: sB + sX ready

        // ---- combine partials -> bd ----
        u64 bd[4];
        {
            float4 po = *reinterpret_cast<const float4*>(&sB[((1 - z) * 256 + rest) * 4]);
            float b0 = p0 + po.x, b1 = p1 + po.y, b2 = p2 + po.z, b3 = p3 + po.w;
            bd[0] = pk2(b0, b0); bd[1] = pk2(b1, b1);
            bd[2] = pk2(b2, b2); bd[3] = pk2(b3, b3);
        }

        // ---- step 3: yp[o0'-pair] += sum_r1 B[r1]*c0[k,r1,z,o0'] (broadcast loads) ----
        #pragma unroll
        for (int r1 = 0; r1 < 4; r1++) {
            const ulonglong2* cq = reinterpret_cast<const ulonglong2*>(
                &sc0[k * 128 + r1 * 32 + z * 16]);
            #pragma unroll
            for (int q = 0; q < 4; q++) {
                ulonglong2 c = cq[q];            // o0' = 4q..4q+3
                yp[2 * q]     = fma2(bd[r1], c.x, yp[2 * q]);
                yp[2 * q + 1] = fma2(bd[r1], c.y, yp[2 * q + 1]);
            }
        }

        // ---- step 1 for slice k+1 into the other sA buffer ----
        if (k < 15) {
            if (k < 14 && tid < 256) xnext = xrow[(i0base + k + 2) * 256 + tid];
            const float4* xq = reinterpret_cast<const float4*>(&sX[(k + 1) & 1][o1 * 16]);
            float4 x0 = xq[0], x1 = xq[1], x2 = xq[2], x3 = xq[3];
            float xs[16] = { x0.x,x0.y,x0.z,x0.w, x1.x,x1.y,x1.z,x1.w,
                             x2.x,x2.y,x2.z,x2.w, x3.x,x3.y,x3.z,x3.w };
            u64 acc0 = 0ull, acc1 = 0ull;
            #pragma unroll
            for (int i2 = 0; i2 < 16; i2 += 2) {
                u64 c0v = *reinterpret_cast<const u64*>(&sc2[i2 * 64 + o2 * 4 + z * 2]);
                u64 c1v = *reinterpret_cast<const u64*>(&sc2[(i2 + 1) * 64 + o2 * 4 + z * 2]);
                acc0 = fma2(pk2(xs[i2], xs[i2]), c0v, acc0);
                acc1 = fma2(pk2(xs[i2 + 1], xs[i2 + 1]), c1v, acc1);
            }
            *reinterpret_cast<u64*>(&sA[(k + 1) & 1][aoff]) = add2(acc0, acc1);
            __syncthreads();                     // S2: sA[(k+1)&1] ready
        }
    }

    // ---- epilogue: RED.ADD y into out (bias pre-written by bias kernel) ----
    float* obase = out + token * 8192 + z * 16 * 256 + rest;
    #pragma unroll
    for (int q = 0; q < 4; q++) {
        float f0, f1, f2, f3;
        unpk(yp[2 * q],     f0, f1);
        unpk(yp[2 * q + 1], f2, f3);
        atomicAdd(obase + (4 * q + 0) * 256, f0);
        atomicAdd(obase + (4 * q + 1) * 256, f1);
        atomicAdd(obase + (4 * q + 2) * 256, f2);
        atomicAdd(obase + (4 * q + 3) * 256, f3);
    }
}

__global__ __launch_bounds__(128)
void tt_bias_kernel(const float* __restrict__ bias, float* __restrict__ out)
{
    // out = 262144 float4 = 128 copies of bias (2048 float4 each)
    const int v = blockIdx.x * 128 + threadIdx.x;        // grid 2048
    reinterpret_cast<float4*>(out)[v] =
        reinterpret_cast<const float4*>(bias)[v & 2047];
}

extern "C" void kernel_launch(void* const* d_in, const int* in_sizes, int n_in,
                              void* d_out, int out_size)
{
    const float* x    = (const float*)d_in[0];  // [128, 8192]
    const float* g0   = (const float*)d_in[1];  // [1,32,32,4]
    const float* g1   = (const float*)d_in[2];  // [4,16,16,4]
    const float* g2   = (const float*)d_in[3];  // [4,16,16,1]
    const float* bias = (const float*)d_in[4];  // [8192]
    float* out = (float*)d_out;                 // [128, 8192]

    tt_bias_kernel<<<2048, 128>>>(bias, out);
    tt_partial_kernel<<<256, THREADS>>>(x, g0, g1, g2, out);
}

// round 9
// speedup vs baseline: 1.2159x; 1.2159x over previous
#include <cuda_runtime.h>

// TT-linear: y = x @ W^T + bias
//   c0: [1,32(o0),32(i0),4(r1)]  c1: [4(r1),16(o1),16(i1),4(r2)]  c2: [4(r2),16(o2),16(i2),1]
//
// Kernel 0: out = bias (broadcast fill).
// Kernel 1: grid 512 = (token 128) x (i0-half 2) x (o1-half 2); 128 thr = (o1p 8, o2 16);
//   __launch_bounds__(128,4) -> 4 independent CTAs/SM, barriers align only 4 warps.
//   16 slices/CTA, ONE __syncthreads per slice (double-buffered sA, sX).
//   step1: thread produces A[i1,{r2},o2] for i1 = o1p and o1p+8 (c2 loads shared)
//   step2: B[r1] via 8 independent fma2 chains, CTA-local c1 (own 8 o1 only)
//   step3: yp[o0-pairs] += B via fma2, broadcast c0 loads
//   Epilogue: RED.ADD y into out (bias already there; 2 REDs land per element).

#define THREADS 128

typedef unsigned long long u64;

__device__ __forceinline__ u64 pk2(float lo, float hi) {
    u64 r;
    asm("mov.b64 %0, {%1, %2};" : "=l"(r) : "f"(lo), "f"(hi));
    return r;
}
__device__ __forceinline__ void unpk(u64 v, float& lo, float& hi) {
    asm("mov.b64 {%0, %1}, %2;" : "=f"(lo), "=f"(hi) : "l"(v));
}
__device__ __forceinline__ u64 fma2(u64 a, u64 b, u64 c) {
    u64 d;
    asm("fma.rn.f32x2 %0, %1, %2, %3;" : "=l"(d) : "l"(a), "l"(b), "l"(c));
    return d;
}
__device__ __forceinline__ float hadd(u64 v) {
    float lo, hi;
    unpk(v, lo, hi);
    return lo + hi;
}

__global__ __launch_bounds__(THREADS, 4)
void tt_partial_kernel(const float* __restrict__ x,
                       const float* __restrict__ g0,
                       const float* __restrict__ g1,
                       const float* __restrict__ g2,
                       float* __restrict__ out)
{
    __shared__ __align__(16) float sc0[2048];    // [it 0..15][r1][o0]
    __shared__ __align__(16) float sc1[2048];    // [o1p 0..7][i1][r1][r2]
    __shared__ __align__(16) float sc2[1024];    // [i2][o2][r2]  (conflict-free)
    __shared__ __align__(16) float sA[2][1024];  // [i1][o2][r2]
    __shared__ __align__(16) float sX[2][256];   // x slices (double buffer)

    const int tid    = threadIdx.x;
    const int token  = blockIdx.x & 127;
    const int half   = (blockIdx.x >> 7) & 1;
    const int o1h    = blockIdx.x >> 8;           // 0 or 1
    const int o2     = tid & 15;
    const int o1p    = tid >> 4;                  // 0..7
    const int i0base = half * 16;

    // ---- core relayout into smem (stride 128) ----
    for (int idx = tid; idx < 2048; idx += THREADS) {
        int o0 = idx & 31, r1 = (idx >> 5) & 3, it = idx >> 7;      // it = 0..15
        sc0[idx] = g0[(o0 * 32 + i0base + it) * 4 + r1];
    }
    for (int idx = tid; idx < 2048; idx += THREADS) {
        int r2 = idx & 3, r1 = (idx >> 2) & 3, i1 = (idx >> 4) & 15, o1g = idx >> 8; // 0..7
        sc1[idx] = g1[((r1 * 16 + o1h * 8 + o1g) * 16 + i1) * 4 + r2];
    }
    for (int idx = tid; idx < 1024; idx += THREADS) {
        int r2 = idx & 3, o2g = (idx >> 2) & 15, i2 = idx >> 6;
        sc2[idx] = g2[(r2 * 16 + o2g) * 16 + i2];                   // -> [(i2*16+o2)*4+r2]
    }

    const float* xrow = x + token * 8192;
    // stage slices 0 and 1 (2 floats per thread each)
    sX[0][tid]       = xrow[(i0base + 0) * 256 + tid];
    sX[0][tid + 128] = xrow[(i0base + 0) * 256 + 128 + tid];
    sX[1][tid]       = xrow[(i0base + 1) * 256 + tid];
    sX[1][tid + 128] = xrow[(i0base + 1) * 256 + 128 + tid];

    u64 yp[16];                           // y[32 o0] as packed pairs for own (o1,o2)
    #pragma unroll
    for (int i = 0; i < 16; i++) yp[i] = 0ull;

    const int i1a = o1p;                  // this thread's two produced A rows
    const int i1b = o1p + 8;

    __syncthreads();

    // ---- prologue: step1 for slice 0 into sA[0] ----
    {
        const float4* xqa = reinterpret_cast<const float4*>(&sX[0][i1a * 16]);
        const float4* xqb = reinterpret_cast<const float4*>(&sX[0][i1b * 16]);
        float4 a0 = xqa[0], a1 = xqa[1], a2 = xqa[2], a3 = xqa[3];
        float4 b0 = xqb[0], b1 = xqb[1], b2 = xqb[2], b3 = xqb[3];
        float xsa[16] = { a0.x,a0.y,a0.z,a0.w, a1.x,a1.y,a1.z,a1.w,
                          a2.x,a2.y,a2.z,a2.w, a3.x,a3.y,a3.z,a3.w };
        float xsb[16] = { b0.x,b0.y,b0.z,b0.w, b1.x,b1.y,b1.z,b1.w,
                          b2.x,b2.y,b2.z,b2.w, b3.x,b3.y,b3.z,b3.w };
        u64 aa01 = 0ull, aa23 = 0ull, ab01 = 0ull, ab23 = 0ull;
        #pragma unroll
        for (int i2 = 0; i2 < 16; i2++) {
            ulonglong2 c = *reinterpret_cast<const ulonglong2*>(&sc2[(i2 * 16 + o2) * 4]);
            u64 xda = pk2(xsa[i2], xsa[i2]);
            u64 xdb = pk2(xsb[i2], xsb[i2]);
            aa01 = fma2(xda, c.x, aa01);  aa23 = fma2(xda, c.y, aa23);
            ab01 = fma2(xdb, c.x, ab01);  ab23 = fma2(xdb, c.y, ab23);
        }
        ulonglong2 sta; sta.x = aa01; sta.y = aa23;
        ulonglong2 stb; stb.x = ab01; stb.y = ab23;
        *reinterpret_cast<ulonglong2*>(&sA[0][(i1a * 16 + o2) * 4]) = sta;
        *reinterpret_cast<ulonglong2*>(&sA[0][(i1b * 16 + o2) * 4]) = stb;
    }
    // registers hold slice 2
    float xn0 = xrow[(i0base + 2) * 256 + tid];
    float xn1 = xrow[(i0base + 2) * 256 + 128 + tid];
    __syncthreads();

    for (int k = 0; k < 16; k++) {
        const float* A = sA[k & 1];

        // ---- step 2: B[r1] = sum_{i1,r2} A[i1,o2,r2] * c1[o1,i1,r1,r2] ----
        u64 acc2[4][2];
        #pragma unroll
        for (int r1 = 0; r1 < 4; r1++) { acc2[r1][0] = 0ull; acc2[r1][1] = 0ull; }
        #pragma unroll
        for (int i1 = 0; i1 < 16; i1++) {
            const ulonglong2 av = *reinterpret_cast<const ulonglong2*>(
                &A[(i1 * 16 + o2) * 4]);                 // (r2 0,1),(r2 2,3)
            const ulonglong2* cp = reinterpret_cast<const ulonglong2*>(
                &sc1[(o1p * 16 + i1) * 16]);             // [r1][(r2 0,1),(r2 2,3)]
            #pragma unroll
            for (int r1 = 0; r1 < 4; r1++) {
                ulonglong2 c = cp[r1];
                acc2[r1][0] = fma2(av.x, c.x, acc2[r1][0]);
                acc2[r1][1] = fma2(av.y, c.y, acc2[r1][1]);
            }
        }
        u64 bd[4];
        #pragma unroll
        for (int r1 = 0; r1 < 4; r1++) {
            float b = hadd(acc2[r1][0]) + hadd(acc2[r1][1]);
            bd[r1] = pk2(b, b);
        }

        // ---- step 3: yp[o0-pair] += sum_r1 B[r1]*c0[k,r1,o0] (broadcast loads) ----
        const ulonglong2* cq = reinterpret_cast<const ulonglong2*>(&sc0[k * 128]);
        #pragma unroll
        for (int q = 0; q < 8; q++) {
            #pragma unroll
            for (int r1 = 0; r1 < 4; r1++) {
                ulonglong2 c = cq[r1 * 8 + q];           // o0 = 4q..4q+3
                yp[2 * q]     = fma2(bd[r1], c.x, yp[2 * q]);
                yp[2 * q + 1] = fma2(bd[r1], c.y, yp[2 * q + 1]);
            }
        }

        // ---- step 1 for slice k+1 into the other sA buffer; stage x k+2 ----
        if (k < 15) {
            const float* Xs = sX[(k + 1) & 1];
            const float4* xqa = reinterpret_cast<const float4*>(&Xs[i1a * 16]);
            const float4* xqb = reinterpret_cast<const float4*>(&Xs[i1b * 16]);
            float4 a0 = xqa[0], a1 = xqa[1], a2 = xqa[2], a3 = xqa[3];
            float4 b0 = xqb[0], b1 = xqb[1], b2 = xqb[2], b3 = xqb[3];
            float xsa[16] = { a0.x,a0.y,a0.z,a0.w, a1.x,a1.y,a1.z,a1.w,
                              a2.x,a2.y,a2.z,a2.w, a3.x,a3.y,a3.z,a3.w };
            float xsb[16] = { b0.x,b0.y,b0.z,b0.w, b1.x,b1.y,b1.z,b1.w,
                              b2.x,b2.y,b2.z,b2.w, b3.x,b3.y,b3.z,b3.w };
            u64 aa01 = 0ull, aa23 = 0ull, ab01 = 0ull, ab23 = 0ull;
            #pragma unroll
            for (int i2 = 0; i2 < 16; i2++) {
                ulonglong2 c = *reinterpret_cast<const ulonglong2*>(&sc2[(i2 * 16 + o2) * 4]);
                u64 xda = pk2(xsa[i2], xsa[i2]);
                u64 xdb = pk2(xsb[i2], xsb[i2]);
                aa01 = fma2(xda, c.x, aa01);  aa23 = fma2(xda, c.y, aa23);
                ab01 = fma2(xdb, c.x, ab01);  ab23 = fma2(xdb, c.y, ab23);
            }
            ulonglong2 sta; sta.x = aa01; sta.y = aa23;
            ulonglong2 stb; stb.x = ab01; stb.y = ab23;
            *reinterpret_cast<ulonglong2*>(&sA[(k + 1) & 1][(i1a * 16 + o2) * 4]) = sta;
            *reinterpret_cast<ulonglong2*>(&sA[(k + 1) & 1][(i1b * 16 + o2) * 4]) = stb;

            // stage slice k+2 into sX[k&1] (its last reader finished before prev barrier)
            if (k < 14) {
                float* Xd = sX[k & 1];
                Xd[tid]       = xn0;
                Xd[tid + 128] = xn1;
                if (k < 13) {
                    xn0 = xrow[(i0base + k + 3) * 256 + tid];
                    xn1 = xrow[(i0base + k + 3) * 256 + 128 + tid];
                }
            }
            __syncthreads();
        }
    }

    // ---- epilogue: RED.ADD y into out (bias pre-filled) ----
    float* obase = out + token * 8192 + o1h * 128 + o1p * 16 + o2;
    #pragma unroll
    for (int q = 0; q < 8; q++) {
        float f0, f1, f2, f3;
        unpk(yp[2 * q],     f0, f1);
        unpk(yp[2 * q + 1], f2, f3);
        atomicAdd(obase + (4 * q + 0) * 256, f0);
        atomicAdd(obase + (4 * q + 1) * 256, f1);
        atomicAdd(obase + (4 * q + 2) * 256, f2);
        atomicAdd(obase + (4 * q + 3) * 256, f3);
    }
}

__global__ __launch_bounds__(128)
void tt_bias_kernel(const float* __restrict__ bias, float* __restrict__ out)
{
    // out = 262144 float4 = 128 copies of bias (2048 float4 each); grid 2048
    const int v = blockIdx.x * 128 + threadIdx.x;
    reinterpret_cast<float4*>(out)[v] =
        reinterpret_cast<const float4*>(bias)[v & 2047];
}

extern "C" void kernel_launch(void* const* d_in, const int* in_sizes, int n_in,
                              void* d_out, int out_size)
{
    const float* x    = (const float*)d_in[0];  // [128, 8192]
    const float* g0   = (const float*)d_in[1];  // [1,32,32,4]
    const float* g1   = (const float*)d_in[2];  // [4,16,16,4]
    const float* g2   = (const float*)d_in[3];  // [4,16,16,1]
    const float* bias = (const float*)d_in[4];  // [8192]
    float* out = (float*)d_out;                 // [128, 8192]

    tt_bias_kernel<<<2048, 128>>>(bias, out);
    tt_partial_kernel<<<512, THREADS>>>(x, g0, g1, g2, out);
}

// round 10
// speedup vs baseline: 1.5602x; 1.2831x over previous
#include <cuda_runtime.h>

// TT-linear: y = x @ W^T + bias
//   c0: [1,32(o0),32(i0),4(r1)]  c1: [4(r1),16(o1),16(i1),4(r2)]  c2: [4(r2),16(o2),16(i2),1]
//
// Kernel 0: out = bias (broadcast fill).
// Kernel 1: grid 256 = (token-pair 64) x (i0-half 2) x (o1-half 2); 256 thr.
//   Lane map: o2 = tid&15, z = (tid>>4)&1, o1p = tid>>5  (warp = 16 o2 x 2 z, fixed o1p).
//   T=2 tokens per CTA: every coefficient smem load feeds both tokens.
//   step1: thread produces A[i1 = 2*o1p+z] rows for both tokens (shared c2 loads).
//   step2: z splits i1-range (8 each); c1 loads are whole-warp broadcasts;
//          partial B combined with shfl_xor(lane^16) — no extra barrier.
//   step3: z splits o0-range; c0 loads shared across tokens.
//   ONE __syncthreads per slice. Epilogue: RED.ADD into bias-prefilled out.

#define THREADS 256

typedef unsigned long long u64;

__device__ __forceinline__ u64 pk2(float lo, float hi) {
    u64 r;
    asm("mov.b64 %0, {%1, %2};" : "=l"(r) : "f"(lo), "f"(hi));
    return r;
}
__device__ __forceinline__ void unpk(u64 v, float& lo, float& hi) {
    asm("mov.b64 {%0, %1}, %2;" : "=f"(lo), "=f"(hi) : "l"(v));
}
__device__ __forceinline__ u64 fma2(u64 a, u64 b, u64 c) {
    u64 d;
    asm("fma.rn.f32x2 %0, %1, %2, %3;" : "=l"(d) : "l"(a), "l"(b), "l"(c));
    return d;
}
__device__ __forceinline__ float hadd(u64 v) {
    float lo, hi;
    unpk(v, lo, hi);
    return lo + hi;
}

// step1: A_t[i1][o2][r2] = sum_i2 x_t[i1*16+i2] * c2[r2,o2,i2] for one (i1, tok)
__device__ __forceinline__ void step1_row(const float* __restrict__ Xs,
                                          float* __restrict__ Ad,
                                          const float* __restrict__ sc2,
                                          int i1, int o2)
{
    const float4* xq = reinterpret_cast<const float4*>(&Xs[i1 * 16]);
    float4 q0 = xq[0], q1 = xq[1], q2 = xq[2], q3 = xq[3];
    float xs[16] = { q0.x,q0.y,q0.z,q0.w, q1.x,q1.y,q1.z,q1.w,
                     q2.x,q2.y,q2.z,q2.w, q3.x,q3.y,q3.z,q3.w };
    u64 a01 = 0ull, a23 = 0ull;
    #pragma unroll
    for (int i2 = 0; i2 < 16; i2++) {
        ulonglong2 c = *reinterpret_cast<const ulonglong2*>(&sc2[(i2 * 16 + o2) * 4]);
        u64 xd = pk2(xs[i2], xs[i2]);
        a01 = fma2(xd, c.x, a01);
        a23 = fma2(xd, c.y, a23);
    }
    ulonglong2 st; st.x = a01; st.y = a23;
    *reinterpret_cast<ulonglong2*>(&Ad[(i1 * 16 + o2) * 4]) = st;
}

__global__ __launch_bounds__(THREADS, 2)
void tt_partial_kernel(const float* __restrict__ x,
                       const float* __restrict__ g0,
                       const float* __restrict__ g1,
                       const float* __restrict__ g2,
                       float* __restrict__ out)
{
    __shared__ __align__(16) float sc0[2048];       // [it 16][r1 4][o0 32]
    __shared__ __align__(16) float sc1[2048];       // [o1p 8][i1 16][r1 4][r2 4]
    __shared__ __align__(16) float sc2[1024];       // [i2][o2][r2]
    __shared__ __align__(16) float sA[2][2][1024];  // [buf][tok][i1][o2][r2]
    __shared__ __align__(16) float sX[2][2][256];   // [buf][tok][elem]

    const int tid    = threadIdx.x;
    const int o2     = tid & 15;
    const int z      = (tid >> 4) & 1;
    const int o1p    = tid >> 5;                    // 0..7; warp-uniform
    const int pair   = blockIdx.x & 63;
    const int half   = (blockIdx.x >> 6) & 1;
    const int o1h    = blockIdx.x >> 7;
    const int i0base = half * 16;

    // ---- core relayout into smem ----
    for (int idx = tid; idx < 2048; idx += THREADS) {
        int o0 = idx & 31, r1 = (idx >> 5) & 3, it = idx >> 7;
        sc0[idx] = g0[(o0 * 32 + i0base + it) * 4 + r1];
    }
    for (int idx = tid; idx < 2048; idx += THREADS) {
        int r2 = idx & 3, r1 = (idx >> 2) & 3, i1 = (idx >> 4) & 15, og = idx >> 8;
        sc1[idx] = g1[((r1 * 16 + o1h * 8 + og) * 16 + i1) * 4 + r2];
    }
    for (int idx = tid; idx < 1024; idx += THREADS) {
        int r2 = idx & 3, o2g = (idx >> 2) & 15, i2 = idx >> 6;
        sc2[idx] = g2[(r2 * 16 + o2g) * 16 + i2];
    }

    const float* x0 = x + (2 * pair + 0) * 8192;
    const float* x1 = x + (2 * pair + 1) * 8192;

    // stage slices 0 and 1 for both tokens
    sX[0][0][tid] = x0[(i0base + 0) * 256 + tid];
    sX[0][1][tid] = x1[(i0base + 0) * 256 + tid];
    sX[1][0][tid] = x0[(i0base + 1) * 256 + tid];
    sX[1][1][tid] = x1[(i0base + 1) * 256 + tid];

    u64 yp0[8], yp1[8];                   // per-token y, own z o0-half (16 o0 = 8 pairs)
    #pragma unroll
    for (int i = 0; i < 8; i++) { yp0[i] = 0ull; yp1[i] = 0ull; }

    const int i1prod = 2 * o1p + z;       // this thread's produced A row

    __syncthreads();

    // prologue: step1 for slice 0 (both tokens) into sA[0]
    step1_row(sX[0][0], sA[0][0], sc2, i1prod, o2);
    step1_row(sX[0][1], sA[0][1], sc2, i1prod, o2);
    float xn0 = x0[(i0base + 2) * 256 + tid];
    float xn1 = x1[(i0base + 2) * 256 + tid];
    __syncthreads();

    for (int k = 0; k < 16; k++) {
        const int b = k & 1;

        // ---- step 2: partial B over own i1-half, both tokens ----
        u64 a0[4][2], a1[4][2];
        #pragma unroll
        for (int r1 = 0; r1 < 4; r1++) {
            a0[r1][0] = 0ull; a0[r1][1] = 0ull;
            a1[r1][0] = 0ull; a1[r1][1] = 0ull;
        }
        #pragma unroll
        for (int s = 0; s < 8; s++) {
            const int i1 = z * 8 + s;
            const ulonglong2 av0 = *reinterpret_cast<const ulonglong2*>(
                &sA[b][0][(i1 * 16 + o2) * 4]);
            const ulonglong2 av1 = *reinterpret_cast<const ulonglong2*>(
                &sA[b][1][(i1 * 16 + o2) * 4]);
            const ulonglong2* cp = reinterpret_cast<const ulonglong2*>(
                &sc1[o1p * 256 + i1 * 16]);            // warp-broadcast
            #pragma unroll
            for (int r1 = 0; r1 < 4; r1++) {
                ulonglong2 c = cp[r1];
                a0[r1][0] = fma2(av0.x, c.x, a0[r1][0]);
                a0[r1][1] = fma2(av0.y, c.y, a0[r1][1]);
                a1[r1][0] = fma2(av1.x, c.x, a1[r1][0]);
                a1[r1][1] = fma2(av1.y, c.y, a1[r1][1]);
            }
        }
        // combine z-halves via shfl_xor (partner = lane^16), build duplicated B
        u64 bd0[4], bd1[4];
        #pragma unroll
        for (int r1 = 0; r1 < 4; r1++) {
            float p0 = hadd(a0[r1][0]) + hadd(a0[r1][1]);
            float p1 = hadd(a1[r1][0]) + hadd(a1[r1][1]);
            p0 += __shfl_xor_sync(0xffffffffu, p0, 16);
            p1 += __shfl_xor_sync(0xffffffffu, p1, 16);
            bd0[r1] = pk2(p0, p0);
            bd1[r1] = pk2(p1, p1);
        }

        // ---- step 3: own z o0-half, both tokens; c0 loads shared ----
        #pragma unroll
        for (int r1 = 0; r1 < 4; r1++) {
            const ulonglong2* cq = reinterpret_cast<const ulonglong2*>(
                &sc0[k * 128 + r1 * 32 + z * 16]);
            #pragma unroll
            for (int q = 0; q < 4; q++) {
                ulonglong2 c = cq[q];                  // o0' = 4q..4q+3 within half
                yp0[2 * q]     = fma2(bd0[r1], c.x, yp0[2 * q]);
                yp0[2 * q + 1] = fma2(bd0[r1], c.y, yp0[2 * q + 1]);
                yp1[2 * q]     = fma2(bd1[r1], c.x, yp1[2 * q]);
                yp1[2 * q + 1] = fma2(bd1[r1], c.y, yp1[2 * q + 1]);
            }
        }

        // ---- step 1 for slice k+1; stage slice k+2; one sync ----
        if (k < 15) {
            const int nb = (k + 1) & 1;
            step1_row(sX[nb][0], sA[nb][0], sc2, i1prod, o2);
            step1_row(sX[nb][1], sA[nb][1], sc2, i1prod, o2);
            if (k < 14) {
                sX[b][0][tid] = xn0;
                sX[b][1][tid] = xn1;
                if (k < 13) {
                    xn0 = x0[(i0base + k + 3) * 256 + tid];
                    xn1 = x1[(i0base + k + 3) * 256 + tid];
                }
            }
            __syncthreads();
        }
    }

    // ---- epilogue: RED.ADD into bias-prefilled out ----
    const int col = (o1h * 8 + o1p) * 16 + o2;
    float* ob0 = out + (size_t)(2 * pair + 0) * 8192 + (z * 16) * 256 + col;
    float* ob1 = out + (size_t)(2 * pair + 1) * 8192 + (z * 16) * 256 + col;
    #pragma unroll
    for (int q = 0; q < 4; q++) {
        float f0, f1, f2, f3, g0v, g1v, g2v, g3v;
        unpk(yp0[2 * q],     f0, f1);
        unpk(yp0[2 * q + 1], f2, f3);
        unpk(yp1[2 * q],     g0v, g1v);
        unpk(yp1[2 * q + 1], g2v, g3v);
        atomicAdd(ob0 + (4 * q + 0) * 256, f0);
        atomicAdd(ob0 + (4 * q + 1) * 256, f1);
        atomicAdd(ob0 + (4 * q + 2) * 256, f2);
        atomicAdd(ob0 + (4 * q + 3) * 256, f3);
        atomicAdd(ob1 + (4 * q + 0) * 256, g0v);
        atomicAdd(ob1 + (4 * q + 1) * 256, g1v);
        atomicAdd(ob1 + (4 * q + 2) * 256, g2v);
        atomicAdd(ob1 + (4 * q + 3) * 256, g3v);
    }
}

__global__ __launch_bounds__(128)
void tt_bias_kernel(const float* __restrict__ bias, float* __restrict__ out)
{
    // out = 262144 float4 = 128 copies of bias (2048 float4 each); grid 2048
    const int v = blockIdx.x * 128 + threadIdx.x;
    reinterpret_cast<float4*>(out)[v] =
        reinterpret_cast<const float4*>(bias)[v & 2047];
}

extern "C" void kernel_launch(void* const* d_in, const int* in_sizes, int n_in,
                              void* d_out, int out_size)
{
    const float* x    = (const float*)d_in[0];  // [128, 8192]
    const float* g0   = (const float*)d_in[1];  // [1,32,32,4]
    const float* g1   = (const float*)d_in[2];  // [4,16,16,4]
    const float* g2   = (const float*)d_in[3];  // [4,16,16,1]
    const float* bias = (const float*)d_in[4];  // [8192]
    float* out = (float*)d_out;                 // [128, 8192]

    tt_bias_kernel<<<2048, 128>>>(bias, out);
    tt_partial_kernel<<<256, THREADS>>>(x, g0, g1, g2, out);
}